// round 10
// baseline (speedup 1.0000x reference)
#include <cuda_runtime.h>
#include <math.h>

// Problem constants
#define U_ 8192
#define P_ 4096
#define D_ 64
#define B_ 1024
#define H_ 50

typedef unsigned long long ull;

// Packed fp32x2 ops (sm_103a): two independent fp32 lanes, bitwise identical
// to scalar FFMA/FADD per element.
#define FMA2(d, a, b) asm("fma.rn.f32x2 %0, %1, %2, %0;" : "+l"(d) : "l"(a), "l"(b))
#define ADD2(d, s)    asm("add.rn.f32x2 %0, %1, %0;" : "+l"(d) : "l"(s))
#define DUP2(d, s)    asm("mov.b64 %0, {%1, %1};"    : "=l"(d) : "f"(s))

// ---------------- scratch (device globals; no allocations allowed) ----------
__device__ float g_p1s[40L * P_ * D_];  // p1 split-K=8 partials [split][r][P][D]
__device__ float g_p1r[5L * P_ * D_];   // reduced p1 [r][P][D]
__device__ float g_u1[(long)U_ * D_];   // u1[0] only (needed for p2)
__device__ float g_Xu[5L * U_ * D_];    // Xu[r]
__device__ float g_p2[8L * P_ * D_];    // split-K=8 partials of A0^T @ u1[0]
__device__ float g_var[U_];
__device__ float g_uemb[(long)U_ * D_];

struct Ptr5 { const float* p[5]; };

#define AROW 132
#define SM64_BYTES ((2 * (32 * AROW + 32 * 64)) * 4)       // 50176
#define SMF_BYTES  ((2 * (32 * 68 + 32 * 64 + 32 * 64)) * 4) // 50176

// ---------------------------------------------------------------------------
// TRANS GEMM (A^T @ X): C[128m x 64n] tiles, BK=32, double-buffered, 256 thr.
// Used for p1 (split-8) and p2 (split-8). Round-6 proven body, TRANS only.
// Decode: mt = b % mTiles; ks = (b/mTiles) % nSplit; r = (b/mTiles) / nSplit
// ---------------------------------------------------------------------------
__global__ __launch_bounds__(256, 2) void gemm_t(
    Ptr5 a5, const float* __restrict__ Xg,
    float* __restrict__ Cbase, long strideCr, long strideCs,
    int mTiles, int nSplit, int Kchunk)
{
    extern __shared__ float smem[];
    float (*As)[32][AROW] = (float (*)[32][AROW])smem;
    float (*Xs)[32][64]   = (float (*)[32][64])(smem + 2 * 32 * AROW);

    int t = blockIdx.x;
    const int mt   = t % mTiles;
    const int rest = t / mTiles;
    const int ks   = rest % nSplit;
    const int r    = rest / nSplit;

    const float* __restrict__ A = a5.p[r];
    float* __restrict__ C = Cbase + (long)r * strideCr + (long)ks * strideCs;

    const int m0 = mt * 128;
    const int kBegin = ks * Kchunk;
    const int nChunks = Kchunk / 32;

    const int tid  = threadIdx.x;
    const int wid  = tid >> 5;
    const int lane = tid & 31;
    const int mbase = (wid >> 2) * 64 + (lane >> 2) * 8;
    const int nbase = (wid & 3) * 16 + (lane & 3) * 4;

    float4 ra[4], rx[2];

    auto loadG = [&](int k0) {
#pragma unroll
        for (int f = 0; f < 4; f++) {
            int linear = tid + 256 * f;
            int kk = linear >> 5;
            int m4 = (linear & 31) * 4;
            ra[f] = *(const float4*)(A + (size_t)(k0 + kk) * P_ + m0 + m4);
        }
#pragma unroll
        for (int f = 0; f < 2; f++) {
            int linear = tid + 256 * f;
            int kk = linear >> 4;
            int n4 = (linear & 15) * 4;
            rx[f] = *(const float4*)(Xg + (size_t)(k0 + kk) * 64 + n4);
        }
    };

    auto storeS = [&](int buf) {
#pragma unroll
        for (int f = 0; f < 4; f++) {
            int linear = tid + 256 * f;
            int kk = linear >> 5;
            int m4 = (linear & 31) * 4;
            *(float4*)&As[buf][kk][m4] = ra[f];
        }
#pragma unroll
        for (int f = 0; f < 2; f++) {
            int linear = tid + 256 * f;
            int kk = linear >> 4;
            int n4 = (linear & 15) * 4;
            *(float4*)&Xs[buf][kk][n4] = rx[f];
        }
    };

    ull acc2[4][4];
#pragma unroll
    for (int p = 0; p < 4; p++)
#pragma unroll
        for (int j = 0; j < 4; j++) acc2[p][j] = 0ull;

    loadG(kBegin);
    storeS(0);
    __syncthreads();

    int buf = 0;
    for (int c = 0; c < nChunks; c++) {
        if (c + 1 < nChunks) loadG(kBegin + (c + 1) * 32);

        ull lacc2[4][4];
#pragma unroll
        for (int p = 0; p < 4; p++)
#pragma unroll
            for (int j = 0; j < 4; j++) lacc2[p][j] = 0ull;

#pragma unroll
        for (int k = 0; k < 32; k++) {
            const ulonglong2* ap = (const ulonglong2*)&As[buf][k][mbase];
            ulonglong2 q0 = ap[0], q1 = ap[1];
            float4 xv = *(const float4*)&Xs[buf][k][nbase];
            ull b0, b1, b2, b3;
            DUP2(b0, xv.x); DUP2(b1, xv.y); DUP2(b2, xv.z); DUP2(b3, xv.w);
            FMA2(lacc2[0][0], q0.x, b0); FMA2(lacc2[0][1], q0.x, b1);
            FMA2(lacc2[0][2], q0.x, b2); FMA2(lacc2[0][3], q0.x, b3);
            FMA2(lacc2[1][0], q0.y, b0); FMA2(lacc2[1][1], q0.y, b1);
            FMA2(lacc2[1][2], q0.y, b2); FMA2(lacc2[1][3], q0.y, b3);
            FMA2(lacc2[2][0], q1.x, b0); FMA2(lacc2[2][1], q1.x, b1);
            FMA2(lacc2[2][2], q1.x, b2); FMA2(lacc2[2][3], q1.x, b3);
            FMA2(lacc2[3][0], q1.y, b0); FMA2(lacc2[3][1], q1.y, b1);
            FMA2(lacc2[3][2], q1.y, b2); FMA2(lacc2[3][3], q1.y, b3);
        }

#pragma unroll
        for (int p = 0; p < 4; p++)
#pragma unroll
            for (int j = 0; j < 4; j++) ADD2(acc2[p][j], lacc2[p][j]);

        if (c + 1 < nChunks) storeS(buf ^ 1);
        __syncthreads();
        buf ^= 1;
    }

#pragma unroll
    for (int p = 0; p < 4; p++) {
        float2 f[4];
#pragma unroll
        for (int j = 0; j < 4; j++) f[j] = *(float2*)&acc2[p][j];
#pragma unroll
        for (int h = 0; h < 2; h++) {
            int m = m0 + mbase + 2 * p + h;
            long off = (long)m * 64 + nbase;
            float4 v;
            v.x = h ? f[0].y : f[0].x;
            v.y = h ? f[1].y : f[1].x;
            v.z = h ? f[2].y : f[2].x;
            v.w = h ? f[3].y : f[3].x;
            *(float4*)(C + off) = v;
        }
    }
}

// ---------------------------------------------------------------------------
// p1 reduce: sum the 8 split partials (sequential order) into g_p1r.
// ---------------------------------------------------------------------------
__global__ __launch_bounds__(256) void reduce_p1_kernel()
{
    const long PD5_4 = 5L * P_ * D_ / 4;
    long i = (long)blockIdx.x * 256 + threadIdx.x;
    if (i >= PD5_4) return;
    const float4* src = (const float4*)g_p1s;
    float4 s = src[i];
#pragma unroll
    for (int sp = 1; sp < 8; sp++) {
        float4 v = src[(long)sp * PD5_4 + i];
        s.x += v.x; s.y += v.y; s.z += v.z; s.w += v.w;
    }
    ((float4*)g_p1r)[i] = s;
}

// ---------------------------------------------------------------------------
// Fused GEMM: for tile (r, mt): u1 = A_r @ p0, u2 = A_r @ p1r[r],
// Xu = ((u0 + u1) + u2)/3. BM=64, 128 threads, thread tile 8m x (4n x 2).
// u1's per-element FP order identical to previous rounds -> bit-identical.
// ---------------------------------------------------------------------------
__global__ __launch_bounds__(128, 2) void fused_gemm(
    Ptr5 a5,
    const float* __restrict__ p0,     // post_emb [P][64]
    const float* __restrict__ p1r,    // reduced p1 [r][P][64]
    const float* __restrict__ u0,     // user_emb [U][64]
    float* __restrict__ Xu,           // [r][U][64]
    float* __restrict__ u1out)        // [U][64], r==0 only
{
    __shared__ float As [2][32][68];
    __shared__ float Xs1[2][32][64];
    __shared__ float Xs2[2][32][64];

    const int t  = blockIdx.x;
    const int mt = t & 127;           // U/64 = 128 m-tiles
    const int r  = t >> 7;

    const float* __restrict__ A  = a5.p[r];
    const float* __restrict__ X2 = p1r + (long)r * (P_ * (long)D_);

    const int m0 = mt * 64;
    const int tid  = threadIdx.x;
    const int wid  = tid >> 5;
    const int lane = tid & 31;
    const int mbase = (lane >> 2) * 8;             // 0..56
    const int nbase = wid * 16 + (lane & 3) * 4;   // 0..60

    float4 ra[4], rx1[4], rx2[4];

    auto loadG = [&](int k0) {
#pragma unroll
        for (int f = 0; f < 4; f++) {
            int linear = tid + 128 * f;            // 0..511
            int row = linear >> 3;                 // 0..63
            int c4  = (linear & 7) * 4;            // 0..28
            ra[f] = *(const float4*)(A + (size_t)(m0 + row) * P_ + k0 + c4);
        }
#pragma unroll
        for (int f = 0; f < 4; f++) {
            int linear = tid + 128 * f;
            int kk = linear >> 4;                  // 0..31
            int n4 = (linear & 15) * 4;
            rx1[f] = *(const float4*)(p0 + (size_t)(k0 + kk) * 64 + n4);
            rx2[f] = *(const float4*)(X2 + (size_t)(k0 + kk) * 64 + n4);
        }
    };

    auto storeS = [&](int buf) {
#pragma unroll
        for (int f = 0; f < 4; f++) {
            int linear = tid + 128 * f;
            int row = linear >> 3;
            int c4  = (linear & 7) * 4;
            As[buf][c4 + 0][row] = ra[f].x;
            As[buf][c4 + 1][row] = ra[f].y;
            As[buf][c4 + 2][row] = ra[f].z;
            As[buf][c4 + 3][row] = ra[f].w;
        }
#pragma unroll
        for (int f = 0; f < 4; f++) {
            int linear = tid + 128 * f;
            int kk = linear >> 4;
            int n4 = (linear & 15) * 4;
            *(float4*)&Xs1[buf][kk][n4] = rx1[f];
            *(float4*)&Xs2[buf][kk][n4] = rx2[f];
        }
    };

    ull accA[4][4], accB[4][4];
#pragma unroll
    for (int p = 0; p < 4; p++)
#pragma unroll
        for (int j = 0; j < 4; j++) { accA[p][j] = 0ull; accB[p][j] = 0ull; }

    loadG(0);
    storeS(0);
    __syncthreads();

    int buf = 0;
    for (int c = 0; c < P_ / 32; c++) {
        if (c + 1 < P_ / 32) loadG((c + 1) * 32);

        ull laccA[4][4], laccB[4][4];
#pragma unroll
        for (int p = 0; p < 4; p++)
#pragma unroll
            for (int j = 0; j < 4; j++) { laccA[p][j] = 0ull; laccB[p][j] = 0ull; }

#pragma unroll
        for (int k = 0; k < 32; k++) {
            const ulonglong2* ap = (const ulonglong2*)&As[buf][k][mbase];
            ulonglong2 q0 = ap[0], q1 = ap[1];
            float4 x1 = *(const float4*)&Xs1[buf][k][nbase];
            float4 x2 = *(const float4*)&Xs2[buf][k][nbase];
            ull a0, a1, a2, a3, b0, b1, b2, b3;
            DUP2(a0, x1.x); DUP2(a1, x1.y); DUP2(a2, x1.z); DUP2(a3, x1.w);
            DUP2(b0, x2.x); DUP2(b1, x2.y); DUP2(b2, x2.z); DUP2(b3, x2.w);
            FMA2(laccA[0][0], q0.x, a0); FMA2(laccA[0][1], q0.x, a1);
            FMA2(laccA[0][2], q0.x, a2); FMA2(laccA[0][3], q0.x, a3);
            FMA2(laccA[1][0], q0.y, a0); FMA2(laccA[1][1], q0.y, a1);
            FMA2(laccA[1][2], q0.y, a2); FMA2(laccA[1][3], q0.y, a3);
            FMA2(laccA[2][0], q1.x, a0); FMA2(laccA[2][1], q1.x, a1);
            FMA2(laccA[2][2], q1.x, a2); FMA2(laccA[2][3], q1.x, a3);
            FMA2(laccA[3][0], q1.y, a0); FMA2(laccA[3][1], q1.y, a1);
            FMA2(laccA[3][2], q1.y, a2); FMA2(laccA[3][3], q1.y, a3);
            FMA2(laccB[0][0], q0.x, b0); FMA2(laccB[0][1], q0.x, b1);
            FMA2(laccB[0][2], q0.x, b2); FMA2(laccB[0][3], q0.x, b3);
            FMA2(laccB[1][0], q0.y, b0); FMA2(laccB[1][1], q0.y, b1);
            FMA2(laccB[1][2], q0.y, b2); FMA2(laccB[1][3], q0.y, b3);
            FMA2(laccB[2][0], q1.x, b0); FMA2(laccB[2][1], q1.x, b1);
            FMA2(laccB[2][2], q1.x, b2); FMA2(laccB[2][3], q1.x, b3);
            FMA2(laccB[3][0], q1.y, b0); FMA2(laccB[3][1], q1.y, b1);
            FMA2(laccB[3][2], q1.y, b2); FMA2(laccB[3][3], q1.y, b3);
        }

#pragma unroll
        for (int p = 0; p < 4; p++)
#pragma unroll
            for (int j = 0; j < 4; j++) {
                ADD2(accA[p][j], laccA[p][j]);
                ADD2(accB[p][j], laccB[p][j]);
            }

        if (c + 1 < P_ / 32) storeS(buf ^ 1);
        __syncthreads();
        buf ^= 1;
    }

    float* __restrict__ XuR = Xu + (long)r * ((long)U_ * D_);
#pragma unroll
    for (int p = 0; p < 4; p++) {
        float2 fa[4], fb[4];
#pragma unroll
        for (int j = 0; j < 4; j++) {
            fa[j] = *(float2*)&accA[p][j];
            fb[j] = *(float2*)&accB[p][j];
        }
#pragma unroll
        for (int h = 0; h < 2; h++) {
            int m = m0 + mbase + 2 * p + h;
            long off = (long)m * 64 + nbase;
            float u1v[4], u2v[4];
#pragma unroll
            for (int j = 0; j < 4; j++) {
                u1v[j] = h ? fa[j].y : fa[j].x;
                u2v[j] = h ? fb[j].y : fb[j].x;
            }
            float4 xu;
            xu.x = (u0[off + 0] + u1v[0] + u2v[0]) / 3.0f;
            xu.y = (u0[off + 1] + u1v[1] + u2v[1]) / 3.0f;
            xu.z = (u0[off + 2] + u1v[2] + u2v[2]) / 3.0f;
            xu.w = (u0[off + 3] + u1v[3] + u2v[3]) / 3.0f;
            *(float4*)(XuR + off) = xu;
            if (r == 0) {
                float4 u1q; u1q.x = u1v[0]; u1q.y = u1v[1];
                u1q.z = u1v[2]; u1q.w = u1v[3];
                *(float4*)(u1out + off) = u1q;
            }
        }
    }
}

// ---------------------------------------------------------------------------
// Per-user: cosine sims vs 4 relations -> var[u]; user_embedding.
// ---------------------------------------------------------------------------
__global__ __launch_bounds__(256) void user_kernel(const float* __restrict__ W)
{
    const int warp = threadIdx.x >> 5;
    const int lane = threadIdx.x & 31;
    const int u = blockIdx.x * 8 + warp;

    const float* __restrict__ xu0 = g_Xu + (long)u * 64;
    const double b0 = (double)xu0[lane], b1 = (double)xu0[lane + 32];

    double d0 = b0 * b0 + b1 * b1;
#pragma unroll
    for (int o = 16; o; o >>= 1) d0 += __shfl_xor_sync(0xffffffffu, d0, o);
    const double n0 = sqrt(d0);

    float sims[4], x0s[4], x1s[4];
#pragma unroll
    for (int rr = 0; rr < 4; rr++) {
        const float* __restrict__ xr = g_Xu + (long)(rr + 1) * U_ * D_ + (long)u * 64;
        float x0 = xr[lane], x1 = xr[lane + 32];
        x0s[rr] = x0; x1s[rr] = x1;
        double xd0 = (double)x0, xd1 = (double)x1;
        double c = b0 * xd0 + b1 * xd1;
        double n = xd0 * xd0 + xd1 * xd1;
#pragma unroll
        for (int o = 16; o; o >>= 1) {
            c += __shfl_xor_sync(0xffffffffu, c, o);
            n += __shfl_xor_sync(0xffffffffu, n, o);
        }
        double denom = n0 * sqrt(n);
        denom = (denom > 1e-8) ? denom : 1e-8;
        sims[rr] = (float)(c / denom);
    }

    if (lane == 0) {
        float mx = fmaxf(fmaxf(sims[0], sims[1]), fmaxf(sims[2], sims[3]));
        double s[4], sum = 0.0;
#pragma unroll
        for (int rr = 0; rr < 4; rr++) {
            s[rr] = (sims[rr] == mx) ? (double)sims[rr] : 0.0;
            sum += s[rr];
        }
        double mean = sum * 0.25;
        double ss = 0.0;
#pragma unroll
        for (int rr = 0; rr < 4; rr++) { double dd = s[rr] - mean; ss += dd * dd; }
        double stdv = sqrt(ss * (1.0 / 3.0));
        g_var[u] = (float)log(stdv + 1.0);
    }

    const float w0 = W[u * 4 + 0], w1 = W[u * 4 + 1];
    const float w2 = W[u * 4 + 2], w3 = W[u * 4 + 3];
    g_uemb[(long)u * 64 + lane]      = w0 * x0s[0] + w1 * x0s[1] + w2 * x0s[2] + w3 * x0s[3];
    g_uemb[(long)u * 64 + lane + 32] = w0 * x1s[0] + w1 * x1s[1] + w2 * x1s[2] + w3 * x1s[3];
}

// ---------------------------------------------------------------------------
// Gather + output.
// ---------------------------------------------------------------------------
__global__ __launch_bounds__(64) void gather_kernel(
    const float* __restrict__ post_emb,
    const int* __restrict__ src_id,
    const int* __restrict__ rum_id,
    float* __restrict__ out)
{
    const int b = blockIdx.x;
    const int d = threadIdx.x;
    const long PD = (long)P_ * D_;

    int s = src_id[b];
    long soff = (long)s * 64 + d;
    float p1v = g_p1r[soff];                 // reduced p1, r=0 slice
    float p2 = 0.0f;
#pragma unroll
    for (int sp = 0; sp < 8; sp++) p2 += g_p2[(long)sp * PD + soff];
    out[(long)b * 64 + d] = (post_emb[soff] + p1v + p2) / 3.0f;

    float accv = 0.0f, accm = 0.0f, accu = 0.0f;
#pragma unroll 2
    for (int h = 0; h < H_; h++) {
        int id = rum_id[b * H_ + h];
        long off = (long)id * 64 + d;
        float x = g_Xu[off];
        float v = g_var[id];
        accv += v * x;
        accm += x;
        accu += g_uemb[off];
    }
    const long BD = (long)B_ * D_;
    out[BD     + (long)b * 64 + d] = accv;
    out[2 * BD + (long)b * 64 + d] = accu * (1.0f / H_);
    out[3 * BD + (long)b * 64 + d] = accm * (1.0f / H_);
}

// ---------------------------------------------------------------------------
extern "C" void kernel_launch(void* const* d_in, const int* in_sizes, int n_in,
                              void* d_out, int out_size)
{
    const float* A0        = (const float*)d_in[0];
    const float* A1        = (const float*)d_in[1];
    const float* A2        = (const float*)d_in[2];
    const float* A3        = (const float*)d_in[3];
    const float* A4        = (const float*)d_in[4];
    const float* user_emb  = (const float*)d_in[5];
    const float* post_emb  = (const float*)d_in[6];
    const float* user_model= (const float*)d_in[7];
    const int*   src_id    = (const int*)d_in[8];
    // d_in[9] = X_user_id (unused by the reference)
    const int*   rum_id    = (const int*)d_in[10];
    float* out = (float*)d_out;

    float *pp1s, *pp1r, *pu1, *pXu, *pp2;
    cudaGetSymbolAddress((void**)&pp1s, g_p1s);
    cudaGetSymbolAddress((void**)&pp1r, g_p1r);
    cudaGetSymbolAddress((void**)&pu1, g_u1);
    cudaGetSymbolAddress((void**)&pXu, g_Xu);
    cudaGetSymbolAddress((void**)&pp2, g_p2);

    Ptr5 a5; a5.p[0] = A0; a5.p[1] = A1; a5.p[2] = A2; a5.p[3] = A3; a5.p[4] = A4;

    const long PD = (long)P_ * D_;

    cudaFuncSetAttribute(gemm_t, cudaFuncAttributeMaxDynamicSharedMemorySize,
                         SM64_BYTES);

    // P1: p1 partials = A_r^T @ u0, split-K=8: 32 mTiles x 8 splits x 5 r = 1280
    gemm_t<<<32 * 8 * 5, 256, SM64_BYTES>>>(
        a5, user_emb, pp1s, PD, 5 * PD, 32, 8, U_ / 8);

    // R: reduce the 8 p1 partials
    reduce_p1_kernel<<<(int)(5 * PD / 4 / 256), 256>>>();

    // P2: fused u1|u2|Xu: 128 mTiles x 5 r = 640 CTAs
    fused_gemm<<<128 * 5, 128>>>(a5, post_emb, pp1r, user_emb, pXu, pu1);

    // P3: p2 partials = A0^T @ u1[0], split-K=8: 256 CTAs
    gemm_t<<<32 * 8, 256, SM64_BYTES>>>(
        a5, pu1, pp2, 0, PD, 32, 8, U_ / 8);

    // epilogue
    user_kernel<<<U_ / 8, 256>>>(user_model);
    gather_kernel<<<B_, 64>>>(post_emb, src_id, rum_id, out);
}

// round 11
// speedup vs baseline: 1.0009x; 1.0009x over previous
#include <cuda_runtime.h>
#include <math.h>

// Problem constants
#define U_ 8192
#define P_ 4096
#define D_ 64
#define B_ 1024
#define H_ 50

typedef unsigned long long ull;

// Packed fp32x2 ops (sm_103a): two independent fp32 lanes, bitwise identical
// to scalar FFMA/FADD per element.
#define FMA2(d, a, b) asm("fma.rn.f32x2 %0, %1, %2, %0;" : "+l"(d) : "l"(a), "l"(b))
#define ADD2(d, s)    asm("add.rn.f32x2 %0, %1, %0;" : "+l"(d) : "l"(s))
#define DUP2(d, s)    asm("mov.b64 %0, {%1, %1};"    : "=l"(d) : "f"(s))

// ---------------- scratch (device globals; no allocations allowed) ----------
__device__ float g_p1s[40L * P_ * D_];  // p1 split-K=8 partials [split][r][P][D]
__device__ float g_p1r[5L * P_ * D_];   // reduced p1 [r][P][D]
__device__ float g_u1[(long)U_ * D_];   // u1[0] only (needed for p2)
__device__ float g_Xu[5L * U_ * D_];    // Xu[r]
__device__ float g_p2[8L * P_ * D_];    // split-K=8 partials of A0^T @ u1[0]
__device__ float g_var[U_];
__device__ float g_uemb[(long)U_ * D_];

struct Ptr5 { const float* p[5]; };

#define AROW 132
#define SM64_BYTES ((2 * (32 * AROW + 32 * 64)) * 4)       // 50176
#define SMF_BYTES  ((2 * (32 * 68 + 32 * 64 + 32 * 64)) * 4) // 50176

// ---------------------------------------------------------------------------
// TRANS GEMM (A^T @ X): C[128m x 64n] tiles, BK=32, double-buffered, 256 thr.
// Used for p1 (split-8) and p2 (split-8). Round-6 proven body, TRANS only.
// Decode: mt = b % mTiles; ks = (b/mTiles) % nSplit; r = (b/mTiles) / nSplit
// ---------------------------------------------------------------------------
__global__ __launch_bounds__(256, 2) void gemm_t(
    Ptr5 a5, const float* __restrict__ Xg,
    float* __restrict__ Cbase, long strideCr, long strideCs,
    int mTiles, int nSplit, int Kchunk)
{
    extern __shared__ float smem[];
    float (*As)[32][AROW] = (float (*)[32][AROW])smem;
    float (*Xs)[32][64]   = (float (*)[32][64])(smem + 2 * 32 * AROW);

    int t = blockIdx.x;
    const int mt   = t % mTiles;
    const int rest = t / mTiles;
    const int ks   = rest % nSplit;
    const int r    = rest / nSplit;

    const float* __restrict__ A = a5.p[r];
    float* __restrict__ C = Cbase + (long)r * strideCr + (long)ks * strideCs;

    const int m0 = mt * 128;
    const int kBegin = ks * Kchunk;
    const int nChunks = Kchunk / 32;

    const int tid  = threadIdx.x;
    const int wid  = tid >> 5;
    const int lane = tid & 31;
    const int mbase = (wid >> 2) * 64 + (lane >> 2) * 8;
    const int nbase = (wid & 3) * 16 + (lane & 3) * 4;

    float4 ra[4], rx[2];

    auto loadG = [&](int k0) {
#pragma unroll
        for (int f = 0; f < 4; f++) {
            int linear = tid + 256 * f;
            int kk = linear >> 5;
            int m4 = (linear & 31) * 4;
            ra[f] = *(const float4*)(A + (size_t)(k0 + kk) * P_ + m0 + m4);
        }
#pragma unroll
        for (int f = 0; f < 2; f++) {
            int linear = tid + 256 * f;
            int kk = linear >> 4;
            int n4 = (linear & 15) * 4;
            rx[f] = *(const float4*)(Xg + (size_t)(k0 + kk) * 64 + n4);
        }
    };

    auto storeS = [&](int buf) {
#pragma unroll
        for (int f = 0; f < 4; f++) {
            int linear = tid + 256 * f;
            int kk = linear >> 5;
            int m4 = (linear & 31) * 4;
            *(float4*)&As[buf][kk][m4] = ra[f];
        }
#pragma unroll
        for (int f = 0; f < 2; f++) {
            int linear = tid + 256 * f;
            int kk = linear >> 4;
            int n4 = (linear & 15) * 4;
            *(float4*)&Xs[buf][kk][n4] = rx[f];
        }
    };

    ull acc2[4][4];
#pragma unroll
    for (int p = 0; p < 4; p++)
#pragma unroll
        for (int j = 0; j < 4; j++) acc2[p][j] = 0ull;

    loadG(kBegin);
    storeS(0);
    __syncthreads();

    int buf = 0;
    for (int c = 0; c < nChunks; c++) {
        if (c + 1 < nChunks) loadG(kBegin + (c + 1) * 32);

        ull lacc2[4][4];
#pragma unroll
        for (int p = 0; p < 4; p++)
#pragma unroll
            for (int j = 0; j < 4; j++) lacc2[p][j] = 0ull;

#pragma unroll
        for (int k = 0; k < 32; k++) {
            const ulonglong2* ap = (const ulonglong2*)&As[buf][k][mbase];
            ulonglong2 q0 = ap[0], q1 = ap[1];
            float4 xv = *(const float4*)&Xs[buf][k][nbase];
            ull b0, b1, b2, b3;
            DUP2(b0, xv.x); DUP2(b1, xv.y); DUP2(b2, xv.z); DUP2(b3, xv.w);
            FMA2(lacc2[0][0], q0.x, b0); FMA2(lacc2[0][1], q0.x, b1);
            FMA2(lacc2[0][2], q0.x, b2); FMA2(lacc2[0][3], q0.x, b3);
            FMA2(lacc2[1][0], q0.y, b0); FMA2(lacc2[1][1], q0.y, b1);
            FMA2(lacc2[1][2], q0.y, b2); FMA2(lacc2[1][3], q0.y, b3);
            FMA2(lacc2[2][0], q1.x, b0); FMA2(lacc2[2][1], q1.x, b1);
            FMA2(lacc2[2][2], q1.x, b2); FMA2(lacc2[2][3], q1.x, b3);
            FMA2(lacc2[3][0], q1.y, b0); FMA2(lacc2[3][1], q1.y, b1);
            FMA2(lacc2[3][2], q1.y, b2); FMA2(lacc2[3][3], q1.y, b3);
        }

#pragma unroll
        for (int p = 0; p < 4; p++)
#pragma unroll
            for (int j = 0; j < 4; j++) ADD2(acc2[p][j], lacc2[p][j]);

        if (c + 1 < nChunks) storeS(buf ^ 1);
        __syncthreads();
        buf ^= 1;
    }

#pragma unroll
    for (int p = 0; p < 4; p++) {
        float2 f[4];
#pragma unroll
        for (int j = 0; j < 4; j++) f[j] = *(float2*)&acc2[p][j];
#pragma unroll
        for (int h = 0; h < 2; h++) {
            int m = m0 + mbase + 2 * p + h;
            long off = (long)m * 64 + nbase;
            float4 v;
            v.x = h ? f[0].y : f[0].x;
            v.y = h ? f[1].y : f[1].x;
            v.z = h ? f[2].y : f[2].x;
            v.w = h ? f[3].y : f[3].x;
            *(float4*)(C + off) = v;
        }
    }
}

// ---------------------------------------------------------------------------
// p1 reduce: sum the 8 split partials (sequential order) into g_p1r.
// ---------------------------------------------------------------------------
__global__ __launch_bounds__(256) void reduce_p1_kernel()
{
    const long PD5_4 = 5L * P_ * D_ / 4;
    long i = (long)blockIdx.x * 256 + threadIdx.x;
    if (i >= PD5_4) return;
    const float4* src = (const float4*)g_p1s;
    float4 s = src[i];
#pragma unroll
    for (int sp = 1; sp < 8; sp++) {
        float4 v = src[(long)sp * PD5_4 + i];
        s.x += v.x; s.y += v.y; s.z += v.z; s.w += v.w;
    }
    ((float4*)g_p1r)[i] = s;
}

// ---------------------------------------------------------------------------
// Fused GEMM: for tile (r, mt): u1 = A_r @ p0, u2 = A_r @ p1r[r],
// Xu = ((u0 + u1) + u2)/3. BM=64, 128 threads, thread tile 8m x (4n x 2).
// u1's per-element FP order identical to previous rounds -> bit-identical.
// ---------------------------------------------------------------------------
__global__ __launch_bounds__(128, 2) void fused_gemm(
    Ptr5 a5,
    const float* __restrict__ p0,     // post_emb [P][64]
    const float* __restrict__ p1r,    // reduced p1 [r][P][64]
    const float* __restrict__ u0,     // user_emb [U][64]
    float* __restrict__ Xu,           // [r][U][64]
    float* __restrict__ u1out)        // [U][64], r==0 only
{
    __shared__ float As [2][32][68];
    __shared__ float Xs1[2][32][64];
    __shared__ float Xs2[2][32][64];

    const int t  = blockIdx.x;
    const int mt = t & 127;           // U/64 = 128 m-tiles
    const int r  = t >> 7;

    const float* __restrict__ A  = a5.p[r];
    const float* __restrict__ X2 = p1r + (long)r * (P_ * (long)D_);

    const int m0 = mt * 64;
    const int tid  = threadIdx.x;
    const int wid  = tid >> 5;
    const int lane = tid & 31;
    const int mbase = (lane >> 2) * 8;             // 0..56
    const int nbase = wid * 16 + (lane & 3) * 4;   // 0..60

    float4 ra[4], rx1[4], rx2[4];

    auto loadG = [&](int k0) {
#pragma unroll
        for (int f = 0; f < 4; f++) {
            int linear = tid + 128 * f;            // 0..511
            int row = linear >> 3;                 // 0..63
            int c4  = (linear & 7) * 4;            // 0..28
            ra[f] = *(const float4*)(A + (size_t)(m0 + row) * P_ + k0 + c4);
        }
#pragma unroll
        for (int f = 0; f < 4; f++) {
            int linear = tid + 128 * f;
            int kk = linear >> 4;                  // 0..31
            int n4 = (linear & 15) * 4;
            rx1[f] = *(const float4*)(p0 + (size_t)(k0 + kk) * 64 + n4);
            rx2[f] = *(const float4*)(X2 + (size_t)(k0 + kk) * 64 + n4);
        }
    };

    auto storeS = [&](int buf) {
#pragma unroll
        for (int f = 0; f < 4; f++) {
            int linear = tid + 128 * f;
            int row = linear >> 3;
            int c4  = (linear & 7) * 4;
            As[buf][c4 + 0][row] = ra[f].x;
            As[buf][c4 + 1][row] = ra[f].y;
            As[buf][c4 + 2][row] = ra[f].z;
            As[buf][c4 + 3][row] = ra[f].w;
        }
#pragma unroll
        for (int f = 0; f < 4; f++) {
            int linear = tid + 128 * f;
            int kk = linear >> 4;
            int n4 = (linear & 15) * 4;
            *(float4*)&Xs1[buf][kk][n4] = rx1[f];
            *(float4*)&Xs2[buf][kk][n4] = rx2[f];
        }
    };

    ull accA[4][4], accB[4][4];
#pragma unroll
    for (int p = 0; p < 4; p++)
#pragma unroll
        for (int j = 0; j < 4; j++) { accA[p][j] = 0ull; accB[p][j] = 0ull; }

    loadG(0);
    storeS(0);
    __syncthreads();

    int buf = 0;
    for (int c = 0; c < P_ / 32; c++) {
        if (c + 1 < P_ / 32) loadG((c + 1) * 32);

        ull laccA[4][4], laccB[4][4];
#pragma unroll
        for (int p = 0; p < 4; p++)
#pragma unroll
            for (int j = 0; j < 4; j++) { laccA[p][j] = 0ull; laccB[p][j] = 0ull; }

#pragma unroll
        for (int k = 0; k < 32; k++) {
            const ulonglong2* ap = (const ulonglong2*)&As[buf][k][mbase];
            ulonglong2 q0 = ap[0], q1 = ap[1];
            float4 x1 = *(const float4*)&Xs1[buf][k][nbase];
            float4 x2 = *(const float4*)&Xs2[buf][k][nbase];
            ull a0, a1, a2, a3, b0, b1, b2, b3;
            DUP2(a0, x1.x); DUP2(a1, x1.y); DUP2(a2, x1.z); DUP2(a3, x1.w);
            DUP2(b0, x2.x); DUP2(b1, x2.y); DUP2(b2, x2.z); DUP2(b3, x2.w);
            FMA2(laccA[0][0], q0.x, a0); FMA2(laccA[0][1], q0.x, a1);
            FMA2(laccA[0][2], q0.x, a2); FMA2(laccA[0][3], q0.x, a3);
            FMA2(laccA[1][0], q0.y, a0); FMA2(laccA[1][1], q0.y, a1);
            FMA2(laccA[1][2], q0.y, a2); FMA2(laccA[1][3], q0.y, a3);
            FMA2(laccA[2][0], q1.x, a0); FMA2(laccA[2][1], q1.x, a1);
            FMA2(laccA[2][2], q1.x, a2); FMA2(laccA[2][3], q1.x, a3);
            FMA2(laccA[3][0], q1.y, a0); FMA2(laccA[3][1], q1.y, a1);
            FMA2(laccA[3][2], q1.y, a2); FMA2(laccA[3][3], q1.y, a3);
            FMA2(laccB[0][0], q0.x, b0); FMA2(laccB[0][1], q0.x, b1);
            FMA2(laccB[0][2], q0.x, b2); FMA2(laccB[0][3], q0.x, b3);
            FMA2(laccB[1][0], q0.y, b0); FMA2(laccB[1][1], q0.y, b1);
            FMA2(laccB[1][2], q0.y, b2); FMA2(laccB[1][3], q0.y, b3);
            FMA2(laccB[2][0], q1.x, b0); FMA2(laccB[2][1], q1.x, b1);
            FMA2(laccB[2][2], q1.x, b2); FMA2(laccB[2][3], q1.x, b3);
            FMA2(laccB[3][0], q1.y, b0); FMA2(laccB[3][1], q1.y, b1);
            FMA2(laccB[3][2], q1.y, b2); FMA2(laccB[3][3], q1.y, b3);
        }

#pragma unroll
        for (int p = 0; p < 4; p++)
#pragma unroll
            for (int j = 0; j < 4; j++) {
                ADD2(accA[p][j], laccA[p][j]);
                ADD2(accB[p][j], laccB[p][j]);
            }

        if (c + 1 < P_ / 32) storeS(buf ^ 1);
        __syncthreads();
        buf ^= 1;
    }

    float* __restrict__ XuR = Xu + (long)r * ((long)U_ * D_);
#pragma unroll
    for (int p = 0; p < 4; p++) {
        float2 fa[4], fb[4];
#pragma unroll
        for (int j = 0; j < 4; j++) {
            fa[j] = *(float2*)&accA[p][j];
            fb[j] = *(float2*)&accB[p][j];
        }
#pragma unroll
        for (int h = 0; h < 2; h++) {
            int m = m0 + mbase + 2 * p + h;
            long off = (long)m * 64 + nbase;
            float u1v[4], u2v[4];
#pragma unroll
            for (int j = 0; j < 4; j++) {
                u1v[j] = h ? fa[j].y : fa[j].x;
                u2v[j] = h ? fb[j].y : fb[j].x;
            }
            float4 xu;
            xu.x = (u0[off + 0] + u1v[0] + u2v[0]) / 3.0f;
            xu.y = (u0[off + 1] + u1v[1] + u2v[1]) / 3.0f;
            xu.z = (u0[off + 2] + u1v[2] + u2v[2]) / 3.0f;
            xu.w = (u0[off + 3] + u1v[3] + u2v[3]) / 3.0f;
            *(float4*)(XuR + off) = xu;
            if (r == 0) {
                float4 u1q; u1q.x = u1v[0]; u1q.y = u1v[1];
                u1q.z = u1v[2]; u1q.w = u1v[3];
                *(float4*)(u1out + off) = u1q;
            }
        }
    }
}

// ---------------------------------------------------------------------------
// Per-user: cosine sims vs 4 relations -> var[u]; user_embedding.
// ---------------------------------------------------------------------------
__global__ __launch_bounds__(256) void user_kernel(const float* __restrict__ W)
{
    const int warp = threadIdx.x >> 5;
    const int lane = threadIdx.x & 31;
    const int u = blockIdx.x * 8 + warp;

    const float* __restrict__ xu0 = g_Xu + (long)u * 64;
    const double b0 = (double)xu0[lane], b1 = (double)xu0[lane + 32];

    double d0 = b0 * b0 + b1 * b1;
#pragma unroll
    for (int o = 16; o; o >>= 1) d0 += __shfl_xor_sync(0xffffffffu, d0, o);
    const double n0 = sqrt(d0);

    float sims[4], x0s[4], x1s[4];
#pragma unroll
    for (int rr = 0; rr < 4; rr++) {
        const float* __restrict__ xr = g_Xu + (long)(rr + 1) * U_ * D_ + (long)u * 64;
        float x0 = xr[lane], x1 = xr[lane + 32];
        x0s[rr] = x0; x1s[rr] = x1;
        double xd0 = (double)x0, xd1 = (double)x1;
        double c = b0 * xd0 + b1 * xd1;
        double n = xd0 * xd0 + xd1 * xd1;
#pragma unroll
        for (int o = 16; o; o >>= 1) {
            c += __shfl_xor_sync(0xffffffffu, c, o);
            n += __shfl_xor_sync(0xffffffffu, n, o);
        }
        double denom = n0 * sqrt(n);
        denom = (denom > 1e-8) ? denom : 1e-8;
        sims[rr] = (float)(c / denom);
    }

    if (lane == 0) {
        float mx = fmaxf(fmaxf(sims[0], sims[1]), fmaxf(sims[2], sims[3]));
        double s[4], sum = 0.0;
#pragma unroll
        for (int rr = 0; rr < 4; rr++) {
            s[rr] = (sims[rr] == mx) ? (double)sims[rr] : 0.0;
            sum += s[rr];
        }
        double mean = sum * 0.25;
        double ss = 0.0;
#pragma unroll
        for (int rr = 0; rr < 4; rr++) { double dd = s[rr] - mean; ss += dd * dd; }
        double stdv = sqrt(ss * (1.0 / 3.0));
        g_var[u] = (float)log(stdv + 1.0);
    }

    const float w0 = W[u * 4 + 0], w1 = W[u * 4 + 1];
    const float w2 = W[u * 4 + 2], w3 = W[u * 4 + 3];
    g_uemb[(long)u * 64 + lane]      = w0 * x0s[0] + w1 * x0s[1] + w2 * x0s[2] + w3 * x0s[3];
    g_uemb[(long)u * 64 + lane + 32] = w0 * x1s[0] + w1 * x1s[1] + w2 * x1s[2] + w3 * x1s[3];
}

// ---------------------------------------------------------------------------
// Gather + output.
// ---------------------------------------------------------------------------
__global__ __launch_bounds__(64) void gather_kernel(
    const float* __restrict__ post_emb,
    const int* __restrict__ src_id,
    const int* __restrict__ rum_id,
    float* __restrict__ out)
{
    const int b = blockIdx.x;
    const int d = threadIdx.x;
    const long PD = (long)P_ * D_;

    int s = src_id[b];
    long soff = (long)s * 64 + d;
    float p1v = g_p1r[soff];                 // reduced p1, r=0 slice
    float p2 = 0.0f;
#pragma unroll
    for (int sp = 0; sp < 8; sp++) p2 += g_p2[(long)sp * PD + soff];
    out[(long)b * 64 + d] = (post_emb[soff] + p1v + p2) / 3.0f;

    float accv = 0.0f, accm = 0.0f, accu = 0.0f;
#pragma unroll 2
    for (int h = 0; h < H_; h++) {
        int id = rum_id[b * H_ + h];
        long off = (long)id * 64 + d;
        float x = g_Xu[off];
        float v = g_var[id];
        accv += v * x;
        accm += x;
        accu += g_uemb[off];
    }
    const long BD = (long)B_ * D_;
    out[BD     + (long)b * 64 + d] = accv;
    out[2 * BD + (long)b * 64 + d] = accu * (1.0f / H_);
    out[3 * BD + (long)b * 64 + d] = accm * (1.0f / H_);
}

// ---------------------------------------------------------------------------
extern "C" void kernel_launch(void* const* d_in, const int* in_sizes, int n_in,
                              void* d_out, int out_size)
{
    const float* A0        = (const float*)d_in[0];
    const float* A1        = (const float*)d_in[1];
    const float* A2        = (const float*)d_in[2];
    const float* A3        = (const float*)d_in[3];
    const float* A4        = (const float*)d_in[4];
    const float* user_emb  = (const float*)d_in[5];
    const float* post_emb  = (const float*)d_in[6];
    const float* user_model= (const float*)d_in[7];
    const int*   src_id    = (const int*)d_in[8];
    // d_in[9] = X_user_id (unused by the reference)
    const int*   rum_id    = (const int*)d_in[10];
    float* out = (float*)d_out;

    float *pp1s, *pp1r, *pu1, *pXu, *pp2;
    cudaGetSymbolAddress((void**)&pp1s, g_p1s);
    cudaGetSymbolAddress((void**)&pp1r, g_p1r);
    cudaGetSymbolAddress((void**)&pu1, g_u1);
    cudaGetSymbolAddress((void**)&pXu, g_Xu);
    cudaGetSymbolAddress((void**)&pp2, g_p2);

    Ptr5 a5; a5.p[0] = A0; a5.p[1] = A1; a5.p[2] = A2; a5.p[3] = A3; a5.p[4] = A4;

    const long PD = (long)P_ * D_;

    cudaFuncSetAttribute(gemm_t, cudaFuncAttributeMaxDynamicSharedMemorySize,
                         SM64_BYTES);

    // P1: p1 partials = A_r^T @ u0, split-K=8: 32 mTiles x 8 splits x 5 r = 1280
    gemm_t<<<32 * 8 * 5, 256, SM64_BYTES>>>(
        a5, user_emb, pp1s, PD, 5 * PD, 32, 8, U_ / 8);

    // R: reduce the 8 p1 partials
    reduce_p1_kernel<<<(int)(5 * PD / 4 / 256), 256>>>();

    // P2: fused u1|u2|Xu: 128 mTiles x 5 r = 640 CTAs
    fused_gemm<<<128 * 5, 128>>>(a5, post_emb, pp1r, user_emb, pXu, pu1);

    // P3: p2 partials = A0^T @ u1[0], split-K=8: 256 CTAs
    gemm_t<<<32 * 8, 256, SM64_BYTES>>>(
        a5, pu1, pp2, 0, PD, 32, 8, U_ / 8);

    // epilogue
    user_kernel<<<U_ / 8, 256>>>(user_model);
    gather_kernel<<<B_, 64>>>(post_emb, src_id, rum_id, out);
}